// round 7
// baseline (speedup 1.0000x reference)
#include <cuda_runtime.h>
#include <math.h>
#include <stdint.h>

#define B_   32
#define S_   64
#define E_   512
#define H_   1024
#define V_   32000
#define G3H  (3 * H_)
#define NTOK (B_ * S_)
#define BH   (B_ * H_)

// ---------------- scratch (device globals; no allocation allowed) ----------------
__device__ float g_ex[NTOK * E_];     // encoder embeddings  [2048, 512]
__device__ float g_dx[NTOK * E_];     // decoder embeddings  [2048, 512]
__device__ float g_xg[NTOK * G3H];    // precomputed input gates [2048, 3072]
__device__ float g_seqA[NTOK * H_];   // sequence buffer
__device__ float g_seqB[NTOK * H_];   // sequence buffer
__device__ float g_h[8][BH];          // 4 layers x ping-pong hidden state
__device__ float g_AT[NTOK * H_];     // transposed activation scratch  (max 2048x1024)
__device__ float g_WT[(size_t)V_ * H_]; // transposed weight scratch    (max 32000x1024)

// ---------------- helpers ----------------
__device__ __forceinline__ uint32_t smem_u32(const void* p) {
    uint32_t a;
    asm("{ .reg .u64 t; cvta.to.shared.u64 t, %1; cvt.u32.u64 %0, t; }" : "=r"(a) : "l"(p));
    return a;
}
__device__ __forceinline__ void cp16(uint32_t dst, const void* src) {
    asm volatile("cp.async.cg.shared.global [%0], [%1], 16;" :: "r"(dst), "l"(src) : "memory");
}
#define CP_COMMIT() asm volatile("cp.async.commit_group;" ::: "memory")
#define CP_WAIT(n)  asm volatile("cp.async.wait_group %0;" :: "n"(n) : "memory")

// ---------------- embedding gather ----------------
__global__ void embed_kernel(const int* __restrict__ idx,
                             const float* __restrict__ emb,
                             float* __restrict__ out) {
    int tok = blockIdx.x;
    int row = idx[tok];
    const float4* src = (const float4*)(emb + (size_t)row * E_);
    float4* dst = (float4*)(out + (size_t)tok * E_);
    for (int i = threadIdx.x; i < E_ / 4; i += blockDim.x) dst[i] = src[i];
}

// ---------------- transpose: out[C][R] = in[R][C]^T (R,C multiples of 32) ----------------
__global__ __launch_bounds__(256)
void transpose_kernel(const float* __restrict__ in, float* __restrict__ out,
                      int R, int C) {
    __shared__ float t[32][33];
    const int c0 = blockIdx.x * 32;
    const int r0 = blockIdx.y * 32;
    const int x = threadIdx.x;       // 0..31
    const int y = threadIdx.y;       // 0..7
#pragma unroll
    for (int i = 0; i < 32; i += 8)
        t[y + i][x] = in[(size_t)(r0 + y + i) * C + c0 + x];
    __syncthreads();
#pragma unroll
    for (int i = 0; i < 32; i += 8)
        out[(size_t)(c0 + y + i) * R + r0 + x] = t[x][y + i];
}

// ---------------- cp.async SGEMM on transposed operands ----------------
// C[M,N] = AT^T * WT + bias, with AT[K][M], WT[K][N] (both k-major).
// 128x128 tile, BK=8, 256 threads, 8x8/thread; double-buffered smem fed by cp.async
// (no register staging, no transpose in kernel -> low reg count, hidden load latency).
#define BM 128
#define BN 128
#define BK 8

__global__ __launch_bounds__(256)
void sgemm_tn_kernel(const float* __restrict__ AT,
                     const float* __restrict__ WT,
                     const float* __restrict__ bias,
                     float* __restrict__ C,
                     int M, int N, int K) {
    __shared__ float As[2][BK][BM];
    __shared__ float Bs[2][BK][BN];

    const int tid = threadIdx.x;
    const int bm = blockIdx.y * BM;
    const int bn = blockIdx.x * BN;

    // copy mapping: per tile, A and B are each 8 rows x 512B; thread t copies one
    // 16B chunk of each: row = t>>5, segment = (t&31)*4 floats. Fully coalesced.
    const int crow = tid >> 5;
    const int cseg = (tid & 31) << 2;

    const int tx = tid & 15;
    const int ty = tid >> 4;

    const float* Asrc = AT + (size_t)crow * M + bm + cseg;
    const float* Bsrc = WT + (size_t)crow * N + bn + cseg;
    uint32_t aDst0 = smem_u32(&As[0][crow][cseg]);
    uint32_t aDst1 = smem_u32(&As[1][crow][cseg]);
    uint32_t bDst0 = smem_u32(&Bs[0][crow][cseg]);
    uint32_t bDst1 = smem_u32(&Bs[1][crow][cseg]);

    float acc[8][8];
#pragma unroll
    for (int i = 0; i < 8; i++)
#pragma unroll
        for (int j = 0; j < 8; j++) acc[i][j] = 0.f;

    // prologue: tile 0 -> buffer 0
    cp16(aDst0, Asrc);
    cp16(bDst0, Bsrc);
    CP_COMMIT();

    const int T = K >> 3;
    for (int i = 0; i < T; i++) {
        const int buf = i & 1;
        if (i + 1 < T) {
            // issue next tile into the other buffer, then wait for current tile
            if (buf == 0) {
                cp16(aDst1, Asrc + (size_t)(i + 1) * BK * M);
                cp16(bDst1, Bsrc + (size_t)(i + 1) * BK * N);
            } else {
                cp16(aDst0, Asrc + (size_t)(i + 1) * BK * M);
                cp16(bDst0, Bsrc + (size_t)(i + 1) * BK * N);
            }
            CP_COMMIT();
            CP_WAIT(1);
        } else {
            CP_WAIT(0);
        }
        __syncthreads();   // current tile visible to all threads

#pragma unroll
        for (int k = 0; k < BK; k++) {
            float a[8], b[8];
            *(float4*)&a[0] = *(const float4*)&As[buf][k][ty * 4];
            *(float4*)&a[4] = *(const float4*)&As[buf][k][64 + ty * 4];
            *(float4*)&b[0] = *(const float4*)&Bs[buf][k][tx * 4];
            *(float4*)&b[4] = *(const float4*)&Bs[buf][k][64 + tx * 4];
#pragma unroll
            for (int ii = 0; ii < 8; ii++)
#pragma unroll
                for (int jj = 0; jj < 8; jj++) acc[ii][jj] += a[ii] * b[jj];
        }
        __syncthreads();   // done reading buf before it is overwritten
    }

    // epilogue: bias add + vectorized stores
#pragma unroll
    for (int i = 0; i < 8; i++) {
        int m = bm + ((i < 4) ? (ty * 4 + i) : (64 + ty * 4 + (i - 4)));
#pragma unroll
        for (int half = 0; half < 2; half++) {
            int n = bn + half * 64 + tx * 4;
            float4 bv = *(const float4*)(bias + n);
            float4 o;
            o.x = acc[i][half * 4 + 0] + bv.x;
            o.y = acc[i][half * 4 + 1] + bv.y;
            o.z = acc[i][half * 4 + 2] + bv.z;
            o.w = acc[i][half * 4 + 3] + bv.w;
            *(float4*)(C + (size_t)m * N + n) = o;
        }
    }
}

// ---------------- fused GRU time step (unchanged from R1: FFMA/latency floor) ----------------
__global__ __launch_bounds__(256)
void gru_step_kernel(const float* __restrict__ h_prev,
                     const float* __restrict__ Whh,
                     const float* __restrict__ bhh,
                     const float* __restrict__ xg,
                     int t, int zero_init,
                     float* __restrict__ h_next,
                     float* __restrict__ y) {
    extern __shared__ float h_s[];   // [H_][B_] 128 KB

    const int tid = threadIdx.x;
    const int b = tid & 31;
    const int j = (blockIdx.x << 3) + (tid >> 5);

    float accr = bhh[j];
    float accz = bhh[H_ + j];
    float accn = bhh[2 * H_ + j];
    float h_old = 0.f;

    if (!zero_init) {
        for (int i4 = tid; i4 < BH / 4; i4 += 256) {
            int lin = i4 * 4;
            int bb = lin >> 10;
            int kk = lin & (H_ - 1);
            float4 v = *(const float4*)(h_prev + lin);
            h_s[(kk + 0) * B_ + bb] = v.x;
            h_s[(kk + 1) * B_ + bb] = v.y;
            h_s[(kk + 2) * B_ + bb] = v.z;
            h_s[(kk + 3) * B_ + bb] = v.w;
        }
        __syncthreads();

        const float* wr = Whh + (size_t)j * H_;
        const float* wz = Whh + (size_t)(H_ + j) * H_;
        const float* wn = Whh + (size_t)(2 * H_ + j) * H_;

#pragma unroll 8
        for (int k = 0; k < H_; k += 4) {
            float4 r4 = __ldg((const float4*)(wr + k));
            float4 z4 = __ldg((const float4*)(wz + k));
            float4 n4 = __ldg((const float4*)(wn + k));
            float h0 = h_s[(k + 0) * B_ + b];
            float h1 = h_s[(k + 1) * B_ + b];
            float h2 = h_s[(k + 2) * B_ + b];
            float h3 = h_s[(k + 3) * B_ + b];
            accr += h0 * r4.x + h1 * r4.y + h2 * r4.z + h3 * r4.w;
            accz += h0 * z4.x + h1 * z4.y + h2 * z4.z + h3 * z4.w;
            accn += h0 * n4.x + h1 * n4.y + h2 * n4.z + h3 * n4.w;
        }
        h_old = h_s[j * B_ + b];
    }

    const float* xp = xg + ((size_t)b * S_ + t) * G3H;
    float r = 1.f / (1.f + expf(-(xp[j] + accr)));
    float z = 1.f / (1.f + expf(-(xp[H_ + j] + accz)));
    float n = tanhf(xp[2 * H_ + j] + r * accn);
    float hnew = (1.f - z) * n + z * h_old;

    h_next[b * H_ + j] = hnew;
    if (y) y[((size_t)b * S_ + t) * H_ + j] = hnew;
}

// ---------------- driver ----------------
static void run_scan(const float* Whh, const float* bhh, const float* xg,
                     float* hpair, const float* h_init, int zero0, float* yout) {
    for (int t = 0; t < S_; t++) {
        const float* hin;
        int zi = 0;
        if (t == 0) {
            if (zero0) { hin = hpair; zi = 1; }
            else       { hin = h_init; }
        } else {
            hin = hpair + (t & 1) * BH;
        }
        float* hout = hpair + ((t + 1) & 1) * BH;
        gru_step_kernel<<<128, 256, 131072>>>(hin, Whh, bhh, xg, t, zi, hout, yout);
    }
}

// transpose in[R][C] -> out[C][R], then GEMM on transposed operands
static void gemm_tn(const float* Aact, const float* Wrow, const float* bias,
                    float* Cout, float* AT, float* WT, int M, int N, int K) {
    dim3 tpb(32, 8);
    transpose_kernel<<<dim3(K / 32, M / 32), tpb>>>(Aact, AT, M, K);
    transpose_kernel<<<dim3(K / 32, N / 32), tpb>>>(Wrow, WT, N, K);
    dim3 grid(N / BN, M / BM);   // N tiles fastest (R1 ordering)
    sgemm_tn_kernel<<<grid, 256>>>(AT, WT, bias, Cout, M, N, K);
}

extern "C" void kernel_launch(void* const* d_in, const int* in_sizes, int n_in,
                              void* d_out, int out_size) {
    const int*   enc_X   = (const int*)d_in[0];
    const int*   dec_X   = (const int*)d_in[1];
    const float* emb_enc = (const float*)d_in[2];
    const float* emb_dec = (const float*)d_in[3];
    const float* eW0i = (const float*)d_in[4];
    const float* eW0h = (const float*)d_in[5];
    const float* eb0i = (const float*)d_in[6];
    const float* eb0h = (const float*)d_in[7];
    const float* eW1i = (const float*)d_in[8];
    const float* eW1h = (const float*)d_in[9];
    const float* eb1i = (const float*)d_in[10];
    const float* eb1h = (const float*)d_in[11];
    const float* dW0i = (const float*)d_in[12];
    const float* dW0h = (const float*)d_in[13];
    const float* db0i = (const float*)d_in[14];
    const float* db0h = (const float*)d_in[15];
    const float* dW1i = (const float*)d_in[16];
    const float* dW1h = (const float*)d_in[17];
    const float* db1i = (const float*)d_in[18];
    const float* db1h = (const float*)d_in[19];
    const float* fcW  = (const float*)d_in[20];
    const float* fcb  = (const float*)d_in[21];
    float* out = (float*)d_out;

    float *ex, *dx, *xg, *seqA, *seqB, *hb, *AT, *WT;
    cudaGetSymbolAddress((void**)&ex,   g_ex);
    cudaGetSymbolAddress((void**)&dx,   g_dx);
    cudaGetSymbolAddress((void**)&xg,   g_xg);
    cudaGetSymbolAddress((void**)&seqA, g_seqA);
    cudaGetSymbolAddress((void**)&seqB, g_seqB);
    cudaGetSymbolAddress((void**)&hb,   g_h);
    cudaGetSymbolAddress((void**)&AT,   g_AT);
    cudaGetSymbolAddress((void**)&WT,   g_WT);

    cudaFuncSetAttribute(gru_step_kernel,
                         cudaFuncAttributeMaxDynamicSharedMemorySize, 131072);

    // embeddings
    embed_kernel<<<NTOK, 128>>>(enc_X, emb_enc, ex);
    embed_kernel<<<NTOK, 128>>>(dec_X, emb_dec, dx);

    // encoder layer 0
    gemm_tn(ex, eW0i, eb0i, xg, AT, WT, NTOK, G3H, E_);
    run_scan(eW0h, eb0h, xg, hb + 0 * 2 * BH, nullptr, 1, seqA);

    // encoder layer 1 (only final hidden needed)
    gemm_tn(seqA, eW1i, eb1i, xg, AT, WT, NTOK, G3H, H_);
    run_scan(eW1h, eb1h, xg, hb + 1 * 2 * BH, nullptr, 1, nullptr);

    // decoder layer 0 (init = enc layer0 final hidden)
    gemm_tn(dx, dW0i, db0i, xg, AT, WT, NTOK, G3H, E_);
    run_scan(dW0h, db0h, xg, hb + 2 * 2 * BH, hb + 0 * 2 * BH, 0, seqA);

    // decoder layer 1 (init = enc layer1 final hidden)
    gemm_tn(seqA, dW1i, db1i, xg, AT, WT, NTOK, G3H, H_);
    run_scan(dW1h, db1h, xg, hb + 3 * 2 * BH, hb + 1 * 2 * BH, 0, seqB);

    // final projection to vocab
    gemm_tn(seqB, fcW, fcb, out, AT, WT, NTOK, V_, H_);
}